// round 15
// baseline (speedup 1.0000x reference)
#include <cuda_runtime.h>
#include <cuda_bf16.h>
#include <cuda_fp16.h>
#include <math.h>
#include <stdint.h>

#define NN 50000
#define EE 800000
#define DD 128
#define BN_EPS 1e-5f
#define NB 196          // ceil(NN/256) scan blocks

// ---------------- device scratch (no allocations allowed) ----------------
__device__ __half g_h[(size_t)NN * DD];   // post-GEMM activations (fp16)
__device__ __half g_agg[(size_t)NN * DD]; // aggregated (fp16)
__device__ __nv_bfloat16 g_wh[3][DD * DD];  // per-layer W^T hi [n][k]
__device__ __nv_bfloat16 g_wl[3][DD * DD];  // per-layer W^T lo [n][k]
__device__ int   g_deg[NN];
__device__ float g_dinv[NN];
__device__ int   g_rowptr[NN + 1];
__device__ int   g_rowcur[NN];
__device__ uint2 g_cw[EE];                // packed {col, w-bits} per edge
__device__ int   g_bsum[256];
__device__ float g_sum[2][DD];            // double-buffered BN stats
__device__ float g_sumsq[2][DD];

// ---------------- block-local edge dtype detect (int32 vs int64) --------
// int64 node ids < 2^31 -> every odd int32 slot of the first elements is 0.
__device__ __forceinline__ int detect_is64_block(const int* __restrict__ ei,
                                                 int* s_flag) {
    if (threadIdx.x == 0) {
        int is64 = 1;
        #pragma unroll
        for (int j = 1; j < 16; j += 2)
            if (ei[j] != 0) is64 = 0;
        *s_flag = is64;
    }
    __syncthreads();
    return *s_flag;
}

__device__ __forceinline__ int edge_src(const int* ei, int e, int is64) {
    return is64 ? ei[2 * e] : ei[e];
}
__device__ __forceinline__ int edge_dst(const int* ei, int e, int is64) {
    return is64 ? ei[2 * (EE + e)] : ei[EE + e];
}

// ---------------- graph preprocessing ----------------
__global__ void deg_count_kernel(const int* __restrict__ ei) {
    __shared__ int s64;
    int is64 = detect_is64_block(ei, &s64);
    int e = blockIdx.x * blockDim.x + threadIdx.x;
    if (e < EE) atomicAdd(&g_deg[edge_dst(ei, e, is64)], 1);
}

// per-256-chunk degree sums; block 0 also zeroes BN stats buffers
__global__ __launch_bounds__(256) void blocksum_kernel() {
    int tid = threadIdx.x;
    if (blockIdx.x == 0 && tid < DD) {
        g_sum[0][tid] = 0.0f; g_sumsq[0][tid] = 0.0f;
        g_sum[1][tid] = 0.0f; g_sumsq[1][tid] = 0.0f;
    }
    int i = blockIdx.x * 256 + tid;
    int v = (i < NN) ? g_deg[i] : 0;
    #pragma unroll
    for (int off = 16; off; off >>= 1)
        v += __shfl_xor_sync(0xffffffffu, v, off);
    __shared__ int ws[8];
    if ((tid & 31) == 0) ws[tid >> 5] = v;
    __syncthreads();
    if (tid == 0) {
        int s = 0;
        #pragma unroll
        for (int w = 0; w < 8; w++) s += ws[w];
        g_bsum[blockIdx.x] = s;
    }
}

// merged: per-block offset (sum of lower block sums) + local scan + outputs
__global__ __launch_bounds__(256) void scan_scatter_kernel() {
    __shared__ int sm[256];
    __shared__ int s_base;
    int tid = threadIdx.x;

    // block offset = sum of g_bsum[0 .. blockIdx.x)
    int v = (tid < NB && tid < blockIdx.x) ? g_bsum[tid] : 0;
    sm[tid] = v;
    __syncthreads();
    #pragma unroll
    for (int s = 128; s; s >>= 1) {
        if (tid < s) sm[tid] += sm[tid + s];
        __syncthreads();
    }
    if (tid == 0) s_base = sm[0];
    __syncthreads();

    // local inclusive scan of this block's degrees
    int i = blockIdx.x * 256 + tid;
    int d = (i < NN) ? g_deg[i] : 0;
    sm[tid] = d;
    __syncthreads();
    for (int off = 1; off < 256; off <<= 1) {
        int t = (tid >= off) ? sm[tid - off] : 0;
        __syncthreads();
        sm[tid] += t;
        __syncthreads();
    }
    if (i < NN) {
        int pos = s_base + sm[tid] - d;   // exclusive prefix
        g_rowptr[i] = pos;
        g_rowcur[i] = pos;
        g_dinv[i] = rsqrtf((float)d + 1.0f);   // +1 self loop
    }
    if (blockIdx.x == NB - 1 && tid == 255)
        g_rowptr[NN] = s_base + sm[255];
}

__global__ void fill_kernel(const int* __restrict__ ei) {
    __shared__ int s64;
    int is64 = detect_is64_block(ei, &s64);
    int e = blockIdx.x * blockDim.x + threadIdx.x;
    if (e < EE) {
        int d = edge_dst(ei, e, is64);
        int s = edge_src(ei, e, is64);
        int pos = atomicAdd(&g_rowcur[d], 1);
        float w = g_dinv[s] * g_dinv[d];
        g_cw[pos] = make_uint2((uint32_t)s, __float_as_uint(w));
    }
}

// W[k][n] -> W^T hi/lo [n][k]; layers 2 and 3 in one launch (grid 128)
__global__ void conv_w23_kernel(const float* __restrict__ W2,
                                const float* __restrict__ W3)
{
    int b = blockIdx.x;
    const float* W = (b < 64) ? W2 : W3;
    int layer = (b < 64) ? 1 : 2;
    int i = (b & 63) * 256 + threadIdx.x;
    int n = i >> 7, k = i & 127;
    float v = W[k * DD + n];
    __nv_bfloat16 h = __float2bfloat16(v);
    __nv_bfloat16 l = __float2bfloat16(v - __bfloat162float(h));
    g_wh[layer][i] = h;
    g_wl[layer][i] = l;
}

__global__ void conv_w1_kernel(const float* __restrict__ W1) {
    int i = blockIdx.x * 256 + threadIdx.x;
    int n = i >> 7, k = i & 127;
    float v = W1[k * DD + n];
    __nv_bfloat16 h = __float2bfloat16(v);
    __nv_bfloat16 l = __float2bfloat16(v - __bfloat162float(h));
    g_wh[0][i] = h;
    g_wl[0][i] = l;
}

// ---------------- HMMA GEMM: h[M,128] = act(A)[M,128] @ W[128,128] -----
// mma.sync m16n8k16 bf16 + ldmatrix. Split precision Ah@Wh + Ah@Wl + Al@Wh,
// fp32 accumulate. BN params computed in-block from double-buffered stats;
// BN+ReLU+hi/lo-split fused into A-tile load (fp32 A for layer 1, fp16 A
// for layers 2/3). Output fp16. K in two 64-chunks -> 72KB smem -> occ 2.
// CTA tile 128x128, 8 warps = 4(M) x 2(N), each warp 32x64.

#define PITCH 72
#define KC 64
#define TILEB (128 * PITCH * 2)   // 18432
#define SM_AHI 0
#define SM_ALO TILEB
#define SM_WHI (2 * TILEB)
#define SM_WLO (3 * TILEB)
#define SM_TOTAL (4 * TILEB)      // 73728

static __device__ __forceinline__ uint32_t smem_u32(const void* p) {
    uint32_t a;
    asm("{ .reg .u64 t; cvta.to.shared.u64 t, %1; cvt.u32.u64 %0, t; }"
        : "=r"(a) : "l"(p));
    return a;
}

__device__ __forceinline__ void ldm_x4(uint32_t* r, uint32_t addr) {
    asm volatile("ldmatrix.sync.aligned.m8n8.x4.shared.b16 {%0,%1,%2,%3}, [%4];"
                 : "=r"(r[0]), "=r"(r[1]), "=r"(r[2]), "=r"(r[3]) : "r"(addr));
}

__device__ __forceinline__ void mma16816(float* d, const uint32_t* a,
                                         uint32_t b0, uint32_t b1) {
    asm volatile(
        "mma.sync.aligned.m16n8k16.row.col.f32.bf16.bf16.f32 "
        "{%0,%1,%2,%3}, {%4,%5,%6,%7}, {%8,%9}, {%0,%1,%2,%3};"
        : "+f"(d[0]), "+f"(d[1]), "+f"(d[2]), "+f"(d[3])
        : "r"(a[0]), "r"(a[1]), "r"(a[2]), "r"(a[3]), "r"(b0), "r"(b1));
}

template<bool BN>
__global__ __launch_bounds__(256, 2)
void gemm_mma_kernel(const void* __restrict__ Avoid,
                     const __nv_bfloat16* __restrict__ Wh,
                     const __nv_bfloat16* __restrict__ Wl,
                     const float* __restrict__ gamma,
                     const float* __restrict__ beta,
                     const float* __restrict__ gsum,
                     const float* __restrict__ gsq,
                     __half* __restrict__ C)
{
    extern __shared__ char smem[];
    __shared__ float s_scale[DD];
    __shared__ float s_shift[DD];
    uint32_t sbase = smem_u32(smem);
    int tid = threadIdx.x;
    int wid = tid >> 5;
    int lane = tid & 31;
    int m0blk = blockIdx.x * 128;
    int wm = (wid & 3) * 32;        // warp M offset in tile
    int wn = (wid >> 2) * 64;       // warp N offset in tile

    if (BN && tid < DD) {
        float mu = gsum[tid] * (1.0f / NN);
        float var = gsq[tid] * (1.0f / NN) - mu * mu;
        float sc = gamma[tid] * rsqrtf(var + BN_EPS);
        s_scale[tid] = sc;
        s_shift[tid] = beta[tid] - mu * sc;
    }
    if (BN) __syncthreads();

    float acc[2][8][4];
    #pragma unroll
    for (int mt = 0; mt < 2; mt++)
        #pragma unroll
        for (int nt = 0; nt < 8; nt++)
            #pragma unroll
            for (int q = 0; q < 4; q++) acc[mt][nt][q] = 0.0f;

    // ldmatrix lane address components
    int a_row = (lane & 7) + 8 * ((lane >> 3) & 1);
    int a_kof = 8 * (lane >> 4);
    int b_nof = (lane & 7) + 8 * (lane >> 4);
    int b_kof = 8 * ((lane >> 3) & 1);

    #pragma unroll
    for (int kc = 0; kc < 2; kc++) {
        int kbase = kc * KC;
        if (kc) __syncthreads();    // protect previous chunk's tiles

        // A chunk (128 rows x 64 cols), 8 cols per thread-iteration,
        // fused BN+ReLU+hi/lo split
        for (int idx = tid; idx < 1024; idx += 256) {
            int r = idx >> 3;
            int c8 = (idx & 7) * 8;
            int gc = kbase + c8;
            float a[8];
            if (m0blk + r < NN) {
                if (BN) {
                    const __half* Ah16 = (const __half*)Avoid;
                    uint4 raw = *(const uint4*)(Ah16 + (size_t)(m0blk + r) * DD + gc);
                    float2 f0 = __half22float2(*(__half2*)&raw.x);
                    float2 f1 = __half22float2(*(__half2*)&raw.y);
                    float2 f2 = __half22float2(*(__half2*)&raw.z);
                    float2 f3 = __half22float2(*(__half2*)&raw.w);
                    a[0] = f0.x; a[1] = f0.y; a[2] = f1.x; a[3] = f1.y;
                    a[4] = f2.x; a[5] = f2.y; a[6] = f3.x; a[7] = f3.y;
                } else {
                    const float* Af = (const float*)Avoid;
                    float4 v0 = *(const float4*)(Af + (size_t)(m0blk + r) * DD + gc);
                    float4 v1 = *(const float4*)(Af + (size_t)(m0blk + r) * DD + gc + 4);
                    a[0] = v0.x; a[1] = v0.y; a[2] = v0.z; a[3] = v0.w;
                    a[4] = v1.x; a[5] = v1.y; a[6] = v1.z; a[7] = v1.w;
                }
            } else {
                #pragma unroll
                for (int q = 0; q < 8; q++) a[q] = 0.0f;
            }
            if (BN) {
                #pragma unroll
                for (int q = 0; q < 8; q++)
                    a[q] = fmaxf(fmaf(a[q], s_scale[gc + q], s_shift[gc + q]), 0.0f);
            }
            uint32_t ph[4], pl[4];
            #pragma unroll
            for (int p = 0; p < 4; p++) {
                __nv_bfloat16 h0 = __float2bfloat16(a[2 * p]);
                __nv_bfloat16 h1 = __float2bfloat16(a[2 * p + 1]);
                __nv_bfloat16 l0 = __float2bfloat16(a[2 * p] - __bfloat162float(h0));
                __nv_bfloat16 l1 = __float2bfloat16(a[2 * p + 1] - __bfloat162float(h1));
                ph[p] = (uint32_t)__bfloat16_as_ushort(h0) | ((uint32_t)__bfloat16_as_ushort(h1) << 16);
                pl[p] = (uint32_t)__bfloat16_as_ushort(l0) | ((uint32_t)__bfloat16_as_ushort(l1) << 16);
            }
            size_t boff = ((size_t)r * PITCH + c8) * 2;
            *(uint4*)(smem + SM_AHI + boff) = make_uint4(ph[0], ph[1], ph[2], ph[3]);
            *(uint4*)(smem + SM_ALO + boff) = make_uint4(pl[0], pl[1], pl[2], pl[3]);
        }
        // W chunk (128 n-rows x 64 k) hi+lo: 1024 x 16B each
        for (int idx = tid; idx < 1024; idx += 256) {
            int n = idx >> 3;
            int kq = (idx & 7) * 8;
            uint4 vh = *(const uint4*)(Wh + (size_t)n * DD + kbase + kq);
            uint4 vl = *(const uint4*)(Wl + (size_t)n * DD + kbase + kq);
            size_t boff = ((size_t)n * PITCH + kq) * 2;
            *(uint4*)(smem + SM_WHI + boff) = vh;
            *(uint4*)(smem + SM_WLO + boff) = vl;
        }
        __syncthreads();

        #pragma unroll
        for (int k0 = 0; k0 < KC; k0 += 16) {
            uint32_t aH[2][4], aL[2][4];
            #pragma unroll
            for (int mt = 0; mt < 2; mt++) {
                uint32_t ad = sbase + SM_AHI
                    + ((uint32_t)(wm + mt * 16 + a_row) * PITCH + k0 + a_kof) * 2;
                ldm_x4(aH[mt], ad);
                ldm_x4(aL[mt], ad + (SM_ALO - SM_AHI));
            }
            #pragma unroll
            for (int ng = 0; ng < 4; ng++) {
                uint32_t bH[4], bL[4];
                uint32_t bd = sbase + SM_WHI
                    + ((uint32_t)(wn + ng * 16 + b_nof) * PITCH + k0 + b_kof) * 2;
                ldm_x4(bH, bd);
                ldm_x4(bL, bd + (SM_WLO - SM_WHI));
                #pragma unroll
                for (int mt = 0; mt < 2; mt++)
                    #pragma unroll
                    for (int half = 0; half < 2; half++) {
                        int nt = ng * 2 + half;
                        int s = half * 2;
                        mma16816(acc[mt][nt], aH[mt], bH[s], bH[s + 1]);
                        mma16816(acc[mt][nt], aH[mt], bL[s], bL[s + 1]);
                        mma16816(acc[mt][nt], aL[mt], bH[s], bH[s + 1]);
                    }
            }
        }
    }

    // store accumulators as fp16
    #pragma unroll
    for (int mt = 0; mt < 2; mt++) {
        int row0 = m0blk + wm + mt * 16 + (lane >> 2);
        int row1 = row0 + 8;
        #pragma unroll
        for (int nt = 0; nt < 8; nt++) {
            int col = wn + nt * 8 + (lane & 3) * 2;
            if (row0 < NN)
                *(__half2*)(C + (size_t)row0 * DD + col) =
                    __floats2half2_rn(acc[mt][nt][0], acc[mt][nt][1]);
            if (row1 < NN)
                *(__half2*)(C + (size_t)row1 * DD + col) =
                    __floats2half2_rn(acc[mt][nt][2], acc[mt][nt][3]);
        }
    }
}

// ---------------- fp16 gather helper ----------------
__device__ __forceinline__ void acc_edge(float4& acc, const __half* __restrict__ h,
                                         int s, int lane, float w)
{
    uint2 raw = *(const uint2*)(h + (size_t)s * DD + lane * 4);
    float2 f0 = __half22float2(*(__half2*)&raw.x);
    float2 f1 = __half22float2(*(__half2*)&raw.y);
    acc.x = fmaf(f0.x, w, acc.x);
    acc.y = fmaf(f0.y, w, acc.y);
    acc.z = fmaf(f1.x, w, acc.z);
    acc.w = fmaf(f1.y, w, acc.w);
}

// ---------------- aggregation + fused BN statistics (fp16 out) ----------
__global__ __launch_bounds__(256) void agg_stats_kernel(
    const __half* __restrict__ h, __half* __restrict__ out,
    float* __restrict__ gsum, float* __restrict__ gsq)
{
    __shared__ float ssum[DD];
    __shared__ float ssq[DD];
    int tid = threadIdx.x;
    if (tid < DD) { ssum[tid] = 0.0f; ssq[tid] = 0.0f; }
    __syncthreads();

    int gw = (blockIdx.x * blockDim.x + tid) >> 5;
    int lane = tid & 31;

    if (gw < NN) {
        float di = g_dinv[gw];
        float4 acc = make_float4(0.f, 0.f, 0.f, 0.f);
        acc_edge(acc, h, gw, lane, di * di);   // self loop

        int beg = g_rowptr[gw];
        int end = g_rowptr[gw + 1];
        int e = beg;
        for (; e + 3 < end; e += 4) {
            uint2 c0 = g_cw[e],     c1 = g_cw[e + 1];
            uint2 c2 = g_cw[e + 2], c3 = g_cw[e + 3];
            acc_edge(acc, h, (int)c0.x, lane, __uint_as_float(c0.y));
            acc_edge(acc, h, (int)c1.x, lane, __uint_as_float(c1.y));
            acc_edge(acc, h, (int)c2.x, lane, __uint_as_float(c2.y));
            acc_edge(acc, h, (int)c3.x, lane, __uint_as_float(c3.y));
        }
        for (; e < end; e++) {
            uint2 c = g_cw[e];
            acc_edge(acc, h, (int)c.x, lane, __uint_as_float(c.y));
        }

        // fp16 store (stats stay fp32 from the pre-rounding accumulator)
        uint2 packed;
        *(__half2*)&packed.x = __floats2half2_rn(acc.x, acc.y);
        *(__half2*)&packed.y = __floats2half2_rn(acc.z, acc.w);
        *(uint2*)(out + (size_t)gw * DD + lane * 4) = packed;

        int f = lane * 4;
        atomicAdd(&ssum[f + 0], acc.x);
        atomicAdd(&ssum[f + 1], acc.y);
        atomicAdd(&ssum[f + 2], acc.z);
        atomicAdd(&ssum[f + 3], acc.w);
        atomicAdd(&ssq[f + 0], acc.x * acc.x);
        atomicAdd(&ssq[f + 1], acc.y * acc.y);
        atomicAdd(&ssq[f + 2], acc.z * acc.z);
        atomicAdd(&ssq[f + 3], acc.w * acc.w);
    }
    __syncthreads();
    if (tid < DD) {
        atomicAdd(&gsum[tid], ssum[tid]);
        atomicAdd(&gsq[tid], ssq[tid]);
    }
}

// ---------------- final aggregation + bias + L2 normalize ----------------
__global__ __launch_bounds__(256) void agg_final_kernel(
    const __half* __restrict__ h, const float* __restrict__ b3,
    float* __restrict__ out)
{
    int gw = (blockIdx.x * blockDim.x + threadIdx.x) >> 5;
    int lane = threadIdx.x & 31;
    if (gw >= NN) return;

    float di = g_dinv[gw];
    float4 acc = make_float4(0.f, 0.f, 0.f, 0.f);
    acc_edge(acc, h, gw, lane, di * di);   // self loop

    int beg = g_rowptr[gw];
    int end = g_rowptr[gw + 1];
    int e = beg;
    for (; e + 3 < end; e += 4) {
        uint2 c0 = g_cw[e],     c1 = g_cw[e + 1];
        uint2 c2 = g_cw[e + 2], c3 = g_cw[e + 3];
        acc_edge(acc, h, (int)c0.x, lane, __uint_as_float(c0.y));
        acc_edge(acc, h, (int)c1.x, lane, __uint_as_float(c1.y));
        acc_edge(acc, h, (int)c2.x, lane, __uint_as_float(c2.y));
        acc_edge(acc, h, (int)c3.x, lane, __uint_as_float(c3.y));
    }
    for (; e < end; e++) {
        uint2 c = g_cw[e];
        acc_edge(acc, h, (int)c.x, lane, __uint_as_float(c.y));
    }

    float4 bb = ((const float4*)b3)[lane];
    acc.x += bb.x; acc.y += bb.y; acc.z += bb.z; acc.w += bb.w;
    float ss = acc.x * acc.x + acc.y * acc.y + acc.z * acc.z + acc.w * acc.w;
    #pragma unroll
    for (int off = 16; off; off >>= 1)
        ss += __shfl_xor_sync(0xffffffffu, ss, off);
    float inv = 1.0f / fmaxf(sqrtf(ss), 1e-12f);
    float4 o = make_float4(acc.x * inv, acc.y * inv, acc.z * inv, acc.w * inv);
    *(float4*)(out + (size_t)gw * DD + lane * 4) = o;
}

// ---------------- launch ----------------
extern "C" void kernel_launch(void* const* d_in, const int* in_sizes, int n_in,
                              void* d_out, int out_size)
{
    const float* x   = (const float*)d_in[0];
    const int*   ei  = (const int*)d_in[1];
    const float* W1  = (const float*)d_in[2];
    // b1 = d_in[3]  -- no-op before BatchNorm
    const float* W2  = (const float*)d_in[4];
    // b2 = d_in[5]  -- no-op before BatchNorm
    const float* W3  = (const float*)d_in[6];
    const float* b3  = (const float*)d_in[7];
    const float* g1  = (const float*)d_in[8];
    const float* be1 = (const float*)d_in[9];
    const float* g2  = (const float*)d_in[10];
    const float* be2 = (const float*)d_in[11];
    float* out = (float*)d_out;

    __half* d_h;   cudaGetSymbolAddress((void**)&d_h,   g_h);
    __half* d_agg; cudaGetSymbolAddress((void**)&d_agg, g_agg);
    __nv_bfloat16* d_wh; cudaGetSymbolAddress((void**)&d_wh, g_wh);
    __nv_bfloat16* d_wl; cudaGetSymbolAddress((void**)&d_wl, g_wl);
    float* d_sum; cudaGetSymbolAddress((void**)&d_sum, g_sum);
    float* d_sq;  cudaGetSymbolAddress((void**)&d_sq,  g_sumsq);
    int* d_deg;   cudaGetSymbolAddress((void**)&d_deg, g_deg);
    __nv_bfloat16* wh1 = d_wh,               *wl1 = d_wl;
    __nv_bfloat16* wh2 = d_wh + DD * DD,     *wl2 = d_wl + DD * DD;
    __nv_bfloat16* wh3 = d_wh + 2 * DD * DD, *wl3 = d_wl + 2 * DD * DD;
    float* sum0 = d_sum, *sq0 = d_sq;
    float* sum1 = d_sum + DD, *sq1 = d_sq + DD;

    static cudaStream_t sB = nullptr, sC = nullptr;
    static cudaEvent_t e0 = nullptr, eB = nullptr, eC = nullptr;
    if (!sB) {
        cudaStreamCreateWithFlags(&sB, cudaStreamNonBlocking);
        cudaStreamCreateWithFlags(&sC, cudaStreamNonBlocking);
        cudaEventCreateWithFlags(&e0, cudaEventDisableTiming);
        cudaEventCreateWithFlags(&eB, cudaEventDisableTiming);
        cudaEventCreateWithFlags(&eC, cudaEventDisableTiming);
        cudaFuncSetAttribute(gemm_mma_kernel<false>,
                             cudaFuncAttributeMaxDynamicSharedMemorySize, SM_TOTAL);
        cudaFuncSetAttribute(gemm_mma_kernel<true>,
                             cudaFuncAttributeMaxDynamicSharedMemorySize, SM_TOTAL);
    }

    const int GEMM_GRID = (NN + 127) / 128;   // 391
    const int WARP_GRID = NN / 8;             // 6250

    // ---- fork: preprocessing on sB, layer-2/3 weight conversion on sC ----
    cudaEventRecord(e0, 0);
    cudaStreamWaitEvent(sB, e0, 0);
    cudaStreamWaitEvent(sC, e0, 0);

    cudaMemsetAsync(d_deg, 0, NN * sizeof(int), sB);
    deg_count_kernel<<<(EE + 255) / 256, 256, 0, sB>>>(ei);
    blocksum_kernel<<<NB, 256, 0, sB>>>();      // also zeroes BN stats
    scan_scatter_kernel<<<NB, 256, 0, sB>>>();
    fill_kernel<<<(EE + 255) / 256, 256, 0, sB>>>(ei);
    cudaEventRecord(eB, sB);

    conv_w23_kernel<<<128, 256, 0, sC>>>(W2, W3);
    cudaEventRecord(eC, sC);

    // ---- main stream: layer 1 GEMM overlaps preprocessing ----
    conv_w1_kernel<<<64, 256>>>(W1);
    gemm_mma_kernel<false><<<GEMM_GRID, 256, SM_TOTAL>>>(
        x, wh1, wl1, nullptr, nullptr, nullptr, nullptr, d_h);

    cudaStreamWaitEvent(0, eB, 0);   // CSR + stats-zero ready
    agg_stats_kernel<<<WARP_GRID, 256>>>(d_h, d_agg, sum0, sq0);

    // ---- layer 2 (BN params computed in-block from stats buf 0) ----
    cudaStreamWaitEvent(0, eC, 0);   // W2/W3 conversions ready
    gemm_mma_kernel<true><<<GEMM_GRID, 256, SM_TOTAL>>>(
        d_agg, wh2, wl2, g1, be1, sum0, sq0, d_h);
    agg_stats_kernel<<<WARP_GRID, 256>>>(d_h, d_agg, sum1, sq1);

    // ---- layer 3 (BN from stats buf 1; bias + L2norm fused into agg) ----
    gemm_mma_kernel<true><<<GEMM_GRID, 256, SM_TOTAL>>>(
        d_agg, wh3, wl3, g2, be2, sum1, sq1, d_h);
    agg_final_kernel<<<WARP_GRID, 256>>>(d_h, b3, out);
}

// round 16
// speedup vs baseline: 1.1649x; 1.1649x over previous
#include <cuda_runtime.h>
#include <cuda_bf16.h>
#include <cuda_fp16.h>
#include <math.h>
#include <stdint.h>

#define NN 50000
#define EE 800000
#define DD 128
#define BN_EPS 1e-5f
#define NB 196          // ceil(NN/256) scan blocks

// ---------------- device scratch (no allocations allowed) ----------------
__device__ __half g_h[(size_t)NN * DD];   // post-GEMM activations (fp16)
__device__ __half g_agg[(size_t)NN * DD]; // aggregated (fp16)
__device__ __nv_bfloat16 g_wh[3][DD * DD];  // per-layer W^T hi [n][k]
__device__ __nv_bfloat16 g_wl[3][DD * DD];  // per-layer W^T lo [n][k]
__device__ int   g_deg[NN];
__device__ float g_dinv[NN];
__device__ int   g_rowptr[NN + 1];
__device__ int   g_rowcur[NN];
__device__ int   g_col[EE];
__device__ float g_w[EE];                 // per-edge norm weight
__device__ int   g_bsum[256];
__device__ int   g_boff[256];
__device__ float g_sum[2][DD];            // double-buffered BN stats
__device__ float g_sumsq[2][DD];
__device__ int   g_is64;

// ---------------- edge index access (int32 vs int64 tolerant) -----------
__device__ __forceinline__ int edge_src(const int* ei, int e) {
    return g_is64 ? ei[2 * e] : ei[e];
}
__device__ __forceinline__ int edge_dst(const int* ei, int e) {
    return g_is64 ? ei[2 * (EE + e)] : ei[EE + e];
}

// ---------------- graph preprocessing ----------------
__global__ void init_kernel(const int* __restrict__ ei) {
    int i = blockIdx.x * blockDim.x + threadIdx.x;
    if (i < NN) g_deg[i] = 0;
    if (i < DD) {
        g_sum[0][i] = 0.0f; g_sumsq[0][i] = 0.0f;
        g_sum[1][i] = 0.0f; g_sumsq[1][i] = 0.0f;
    }
    if (i == 0) {
        int is64 = 1;
        #pragma unroll
        for (int j = 1; j < 16; j += 2)
            if (ei[j] != 0) is64 = 0;
        g_is64 = is64;
    }
}

__global__ void deg_count_kernel(const int* __restrict__ ei) {
    int e = blockIdx.x * blockDim.x + threadIdx.x;
    if (e < EE) atomicAdd(&g_deg[edge_dst(ei, e)], 1);
}

__global__ __launch_bounds__(256) void blocksum_kernel() {
    int tid = threadIdx.x;
    int i = blockIdx.x * 256 + tid;
    int v = (i < NN) ? g_deg[i] : 0;
    #pragma unroll
    for (int off = 16; off; off >>= 1)
        v += __shfl_xor_sync(0xffffffffu, v, off);
    __shared__ int ws[8];
    if ((tid & 31) == 0) ws[tid >> 5] = v;
    __syncthreads();
    if (tid == 0) {
        int s = 0;
        #pragma unroll
        for (int w = 0; w < 8; w++) s += ws[w];
        g_bsum[blockIdx.x] = s;
    }
}

__global__ __launch_bounds__(256) void scan_bsums_kernel() {
    __shared__ int sm[256];
    int tid = threadIdx.x;
    int v = (tid < NB) ? g_bsum[tid] : 0;
    sm[tid] = v;
    __syncthreads();
    for (int off = 1; off < 256; off <<= 1) {
        int t = (tid >= off) ? sm[tid - off] : 0;
        __syncthreads();
        sm[tid] += t;
        __syncthreads();
    }
    if (tid < NB) g_boff[tid] = sm[tid] - v;       // exclusive
    if (tid == NB - 1) g_rowptr[NN] = sm[tid];     // total
}

__global__ __launch_bounds__(256) void scatter_scan_kernel() {
    __shared__ int sm[256];
    int tid = threadIdx.x;
    int i = blockIdx.x * 256 + tid;
    int d = (i < NN) ? g_deg[i] : 0;
    sm[tid] = d;
    __syncthreads();
    for (int off = 1; off < 256; off <<= 1) {
        int t = (tid >= off) ? sm[tid - off] : 0;
        __syncthreads();
        sm[tid] += t;
        __syncthreads();
    }
    if (i < NN) {
        int pos = g_boff[blockIdx.x] + sm[tid] - d;
        g_rowptr[i] = pos;
        g_rowcur[i] = pos;
        g_dinv[i] = rsqrtf((float)d + 1.0f);       // +1 self loop
    }
}

__global__ void fill_kernel(const int* __restrict__ ei) {
    int e = blockIdx.x * blockDim.x + threadIdx.x;
    if (e < EE) {
        int d = edge_dst(ei, e);
        int s = edge_src(ei, e);
        int pos = atomicAdd(&g_rowcur[d], 1);
        g_col[pos] = s;
        g_w[pos] = g_dinv[s] * g_dinv[d];
    }
}

// W[k][n] -> W^T hi/lo [n][k]
__global__ void conv_w_kernel(const float* __restrict__ W,
                              __nv_bfloat16* __restrict__ wh,
                              __nv_bfloat16* __restrict__ wl)
{
    int i = blockIdx.x * 256 + threadIdx.x;
    if (i >= DD * DD) return;
    int n = i >> 7, k = i & 127;
    float v = W[k * DD + n];
    __nv_bfloat16 h = __float2bfloat16(v);
    __nv_bfloat16 l = __float2bfloat16(v - __bfloat162float(h));
    wh[i] = h;
    wl[i] = l;
}

// ---------------- HMMA GEMM: h[M,128] = act(A)[M,128] @ W[128,128] -----
// (identical to the 217us baseline)
#define PITCH 72
#define KC 64
#define TILEB (128 * PITCH * 2)   // 18432
#define SM_AHI 0
#define SM_ALO TILEB
#define SM_WHI (2 * TILEB)
#define SM_WLO (3 * TILEB)
#define SM_TOTAL (4 * TILEB)      // 73728

static __device__ __forceinline__ uint32_t smem_u32(const void* p) {
    uint32_t a;
    asm("{ .reg .u64 t; cvta.to.shared.u64 t, %1; cvt.u32.u64 %0, t; }"
        : "=r"(a) : "l"(p));
    return a;
}

__device__ __forceinline__ void ldm_x4(uint32_t* r, uint32_t addr) {
    asm volatile("ldmatrix.sync.aligned.m8n8.x4.shared.b16 {%0,%1,%2,%3}, [%4];"
                 : "=r"(r[0]), "=r"(r[1]), "=r"(r[2]), "=r"(r[3]) : "r"(addr));
}

__device__ __forceinline__ void mma16816(float* d, const uint32_t* a,
                                         uint32_t b0, uint32_t b1) {
    asm volatile(
        "mma.sync.aligned.m16n8k16.row.col.f32.bf16.bf16.f32 "
        "{%0,%1,%2,%3}, {%4,%5,%6,%7}, {%8,%9}, {%0,%1,%2,%3};"
        : "+f"(d[0]), "+f"(d[1]), "+f"(d[2]), "+f"(d[3])
        : "r"(a[0]), "r"(a[1]), "r"(a[2]), "r"(a[3]), "r"(b0), "r"(b1));
}

template<bool BN>
__global__ __launch_bounds__(256, 2)
void gemm_mma_kernel(const void* __restrict__ Avoid,
                     const __nv_bfloat16* __restrict__ Wh,
                     const __nv_bfloat16* __restrict__ Wl,
                     const float* __restrict__ gamma,
                     const float* __restrict__ beta,
                     const float* __restrict__ gsum,
                     const float* __restrict__ gsq,
                     __half* __restrict__ C)
{
    extern __shared__ char smem[];
    __shared__ float s_scale[DD];
    __shared__ float s_shift[DD];
    uint32_t sbase = smem_u32(smem);
    int tid = threadIdx.x;
    int wid = tid >> 5;
    int lane = tid & 31;
    int m0blk = blockIdx.x * 128;
    int wm = (wid & 3) * 32;
    int wn = (wid >> 2) * 64;

    if (BN && tid < DD) {
        float mu = gsum[tid] * (1.0f / NN);
        float var = gsq[tid] * (1.0f / NN) - mu * mu;
        float sc = gamma[tid] * rsqrtf(var + BN_EPS);
        s_scale[tid] = sc;
        s_shift[tid] = beta[tid] - mu * sc;
    }
    if (BN) __syncthreads();

    float acc[2][8][4];
    #pragma unroll
    for (int mt = 0; mt < 2; mt++)
        #pragma unroll
        for (int nt = 0; nt < 8; nt++)
            #pragma unroll
            for (int q = 0; q < 4; q++) acc[mt][nt][q] = 0.0f;

    int a_row = (lane & 7) + 8 * ((lane >> 3) & 1);
    int a_kof = 8 * (lane >> 4);
    int b_nof = (lane & 7) + 8 * (lane >> 4);
    int b_kof = 8 * ((lane >> 3) & 1);

    #pragma unroll
    for (int kc = 0; kc < 2; kc++) {
        int kbase = kc * KC;
        if (kc) __syncthreads();

        for (int idx = tid; idx < 2048; idx += 256) {
            int r = idx >> 4;
            int c4 = (idx & 15) * 4;
            int gc = kbase + c4;
            float4 v = make_float4(0.f, 0.f, 0.f, 0.f);
            if (m0blk + r < NN) {
                if (BN) {
                    const __half* Ah16 = (const __half*)Avoid;
                    uint2 raw = *(const uint2*)(Ah16 + (size_t)(m0blk + r) * DD + gc);
                    float2 f0 = __half22float2(*(__half2*)&raw.x);
                    float2 f1 = __half22float2(*(__half2*)&raw.y);
                    v = make_float4(f0.x, f0.y, f1.x, f1.y);
                } else {
                    const float* Af = (const float*)Avoid;
                    v = *(const float4*)(Af + (size_t)(m0blk + r) * DD + gc);
                }
            }
            if (BN) {
                v.x = fmaxf(fmaf(v.x, s_scale[gc + 0], s_shift[gc + 0]), 0.0f);
                v.y = fmaxf(fmaf(v.y, s_scale[gc + 1], s_shift[gc + 1]), 0.0f);
                v.z = fmaxf(fmaf(v.z, s_scale[gc + 2], s_shift[gc + 2]), 0.0f);
                v.w = fmaxf(fmaf(v.w, s_scale[gc + 3], s_shift[gc + 3]), 0.0f);
            }
            float a[4] = {v.x, v.y, v.z, v.w};
            uint32_t ph[2], pl[2];
            #pragma unroll
            for (int p = 0; p < 2; p++) {
                __nv_bfloat16 h0 = __float2bfloat16(a[2 * p]);
                __nv_bfloat16 h1 = __float2bfloat16(a[2 * p + 1]);
                __nv_bfloat16 l0 = __float2bfloat16(a[2 * p] - __bfloat162float(h0));
                __nv_bfloat16 l1 = __float2bfloat16(a[2 * p + 1] - __bfloat162float(h1));
                ph[p] = (uint32_t)__bfloat16_as_ushort(h0) | ((uint32_t)__bfloat16_as_ushort(h1) << 16);
                pl[p] = (uint32_t)__bfloat16_as_ushort(l0) | ((uint32_t)__bfloat16_as_ushort(l1) << 16);
            }
            size_t boff = ((size_t)r * PITCH + c4) * 2;
            *(uint2*)(smem + SM_AHI + boff) = make_uint2(ph[0], ph[1]);
            *(uint2*)(smem + SM_ALO + boff) = make_uint2(pl[0], pl[1]);
        }
        for (int idx = tid; idx < 1024; idx += 256) {
            int n = idx >> 3;
            int kq = (idx & 7) * 8;
            uint4 vh = *(const uint4*)(Wh + (size_t)n * DD + kbase + kq);
            uint4 vl = *(const uint4*)(Wl + (size_t)n * DD + kbase + kq);
            size_t boff = ((size_t)n * PITCH + kq) * 2;
            *(uint4*)(smem + SM_WHI + boff) = vh;
            *(uint4*)(smem + SM_WLO + boff) = vl;
        }
        __syncthreads();

        #pragma unroll
        for (int k0 = 0; k0 < KC; k0 += 16) {
            uint32_t aH[2][4], aL[2][4];
            #pragma unroll
            for (int mt = 0; mt < 2; mt++) {
                uint32_t ad = sbase + SM_AHI
                    + ((uint32_t)(wm + mt * 16 + a_row) * PITCH + k0 + a_kof) * 2;
                ldm_x4(aH[mt], ad);
                ldm_x4(aL[mt], ad + (SM_ALO - SM_AHI));
            }
            #pragma unroll
            for (int ng = 0; ng < 4; ng++) {
                uint32_t bH[4], bL[4];
                uint32_t bd = sbase + SM_WHI
                    + ((uint32_t)(wn + ng * 16 + b_nof) * PITCH + k0 + b_kof) * 2;
                ldm_x4(bH, bd);
                ldm_x4(bL, bd + (SM_WLO - SM_WHI));
                #pragma unroll
                for (int mt = 0; mt < 2; mt++)
                    #pragma unroll
                    for (int half = 0; half < 2; half++) {
                        int nt = ng * 2 + half;
                        int s = half * 2;
                        mma16816(acc[mt][nt], aH[mt], bH[s], bH[s + 1]);
                        mma16816(acc[mt][nt], aH[mt], bL[s], bL[s + 1]);
                        mma16816(acc[mt][nt], aL[mt], bH[s], bH[s + 1]);
                    }
            }
        }
    }

    #pragma unroll
    for (int mt = 0; mt < 2; mt++) {
        int row0 = m0blk + wm + mt * 16 + (lane >> 2);
        int row1 = row0 + 8;
        #pragma unroll
        for (int nt = 0; nt < 8; nt++) {
            int col = wn + nt * 8 + (lane & 3) * 2;
            if (row0 < NN)
                *(__half2*)(C + (size_t)row0 * DD + col) =
                    __floats2half2_rn(acc[mt][nt][0], acc[mt][nt][1]);
            if (row1 < NN)
                *(__half2*)(C + (size_t)row1 * DD + col) =
                    __floats2half2_rn(acc[mt][nt][2], acc[mt][nt][3]);
        }
    }
}

// ---------------- half-warp gather helper: 8 features per lane ----------
__device__ __forceinline__ void acc8(float* a, const __half* __restrict__ h,
                                     int s, int fl, float w)
{
    uint4 raw = *(const uint4*)(h + (size_t)s * DD + fl);
    const __half2* hp = (const __half2*)&raw;
    #pragma unroll
    for (int p = 0; p < 4; p++) {
        float2 f = __half22float2(hp[p]);
        a[2 * p]     = fmaf(f.x, w, a[2 * p]);
        a[2 * p + 1] = fmaf(f.y, w, a[2 * p + 1]);
    }
}

// ---------------- aggregation + fused BN statistics (half-warp/edge) ----
// One warp per node. Lanes 0-15 process even edges, 16-31 odd edges;
// each lane owns 8 features via one LDG.128 (halves LDG issue count).
__global__ __launch_bounds__(256) void agg_stats_kernel(
    const __half* __restrict__ h, __half* __restrict__ out,
    float* __restrict__ gsum, float* __restrict__ gsq)
{
    __shared__ float ssum[DD];
    __shared__ float ssq[DD];
    int tid = threadIdx.x;
    if (tid < DD) { ssum[tid] = 0.0f; ssq[tid] = 0.0f; }
    __syncthreads();

    int gw = (blockIdx.x * blockDim.x + tid) >> 5;
    int lane = tid & 31;
    int half = lane >> 4;           // 0 or 1
    int fl = (lane & 15) * 8;       // feature base (8 features)

    if (gw < NN) {
        float di = g_dinv[gw];
        float a[8];
        #pragma unroll
        for (int q = 0; q < 8; q++) a[q] = 0.0f;

        int beg = g_rowptr[gw];
        int end = g_rowptr[gw + 1];
        int e = beg + half;
        for (; e + 2 < end; e += 4) {       // this half does e and e+2
            int s0 = g_col[e];      float w0 = g_w[e];
            int s1 = g_col[e + 2];  float w1 = g_w[e + 2];
            acc8(a, h, s0, fl, w0);
            acc8(a, h, s1, fl, w1);
        }
        for (; e < end; e += 2)
            acc8(a, h, g_col[e], fl, g_w[e]);

        // combine halves (lane and lane^16 own the same feature slice)
        #pragma unroll
        for (int q = 0; q < 8; q++)
            a[q] += __shfl_xor_sync(0xffffffffu, a[q], 16);

        if (half == 0) {
            acc8(a, h, gw, fl, di * di);    // self loop

            uint4 packed;
            __half2* pp = (__half2*)&packed;
            #pragma unroll
            for (int p = 0; p < 4; p++)
                pp[p] = __floats2half2_rn(a[2 * p], a[2 * p + 1]);
            *(uint4*)(out + (size_t)gw * DD + fl) = packed;

            #pragma unroll
            for (int q = 0; q < 8; q++) {
                atomicAdd(&ssum[fl + q], a[q]);
                atomicAdd(&ssq[fl + q], a[q] * a[q]);
            }
        }
    }
    __syncthreads();
    if (tid < DD) {
        atomicAdd(&gsum[tid], ssum[tid]);
        atomicAdd(&gsq[tid], ssq[tid]);
    }
}

// ---------------- final aggregation + bias + L2 normalize ----------------
__global__ __launch_bounds__(256) void agg_final_kernel(
    const __half* __restrict__ h, const float* __restrict__ b3,
    float* __restrict__ out)
{
    int gw = (blockIdx.x * blockDim.x + threadIdx.x) >> 5;
    int lane = threadIdx.x & 31;
    int half = lane >> 4;
    int fl = (lane & 15) * 8;
    if (gw >= NN) return;

    float di = g_dinv[gw];
    float a[8];
    #pragma unroll
    for (int q = 0; q < 8; q++) a[q] = 0.0f;

    int beg = g_rowptr[gw];
    int end = g_rowptr[gw + 1];
    int e = beg + half;
    for (; e + 2 < end; e += 4) {
        int s0 = g_col[e];      float w0 = g_w[e];
        int s1 = g_col[e + 2];  float w1 = g_w[e + 2];
        acc8(a, h, s0, fl, w0);
        acc8(a, h, s1, fl, w1);
    }
    for (; e < end; e += 2)
        acc8(a, h, g_col[e], fl, g_w[e]);

    #pragma unroll
    for (int q = 0; q < 8; q++)
        a[q] += __shfl_xor_sync(0xffffffffu, a[q], 16);

    // both halves replicate self+bias+norm math; half 0 stores
    acc8(a, h, gw, fl, di * di);            // self loop
    float4 b0 = *(const float4*)(b3 + fl);
    float4 b1 = *(const float4*)(b3 + fl + 4);
    a[0] += b0.x; a[1] += b0.y; a[2] += b0.z; a[3] += b0.w;
    a[4] += b1.x; a[5] += b1.y; a[6] += b1.z; a[7] += b1.w;

    float ss = 0.0f;
    #pragma unroll
    for (int q = 0; q < 8; q++) ss += a[q] * a[q];
    #pragma unroll
    for (int off = 8; off; off >>= 1)
        ss += __shfl_xor_sync(0xffffffffu, ss, off);   // sums 16-lane group
    float inv = 1.0f / fmaxf(sqrtf(ss), 1e-12f);

    if (half == 0) {
        float4 o0 = make_float4(a[0] * inv, a[1] * inv, a[2] * inv, a[3] * inv);
        float4 o1 = make_float4(a[4] * inv, a[5] * inv, a[6] * inv, a[7] * inv);
        *(float4*)(out + (size_t)gw * DD + fl)     = o0;
        *(float4*)(out + (size_t)gw * DD + fl + 4) = o1;
    }
}

// ---------------- launch ----------------
extern "C" void kernel_launch(void* const* d_in, const int* in_sizes, int n_in,
                              void* d_out, int out_size)
{
    const float* x   = (const float*)d_in[0];
    const int*   ei  = (const int*)d_in[1];
    const float* W1  = (const float*)d_in[2];
    // b1 = d_in[3]  -- no-op before BatchNorm
    const float* W2  = (const float*)d_in[4];
    // b2 = d_in[5]  -- no-op before BatchNorm
    const float* W3  = (const float*)d_in[6];
    const float* b3  = (const float*)d_in[7];
    const float* g1  = (const float*)d_in[8];
    const float* be1 = (const float*)d_in[9];
    const float* g2  = (const float*)d_in[10];
    const float* be2 = (const float*)d_in[11];
    float* out = (float*)d_out;

    __half* d_h;   cudaGetSymbolAddress((void**)&d_h,   g_h);
    __half* d_agg; cudaGetSymbolAddress((void**)&d_agg, g_agg);
    __nv_bfloat16* d_wh; cudaGetSymbolAddress((void**)&d_wh, g_wh);
    __nv_bfloat16* d_wl; cudaGetSymbolAddress((void**)&d_wl, g_wl);
    float* d_sum; cudaGetSymbolAddress((void**)&d_sum, g_sum);
    float* d_sq;  cudaGetSymbolAddress((void**)&d_sq,  g_sumsq);
    __nv_bfloat16* wh1 = d_wh,               *wl1 = d_wl;
    __nv_bfloat16* wh2 = d_wh + DD * DD,     *wl2 = d_wl + DD * DD;
    __nv_bfloat16* wh3 = d_wh + 2 * DD * DD, *wl3 = d_wl + 2 * DD * DD;
    float* sum0 = d_sum, *sq0 = d_sq;
    float* sum1 = d_sum + DD, *sq1 = d_sq + DD;

    static cudaStream_t sB = nullptr, sC = nullptr;
    static cudaEvent_t e0 = nullptr, eB = nullptr, eC = nullptr;
    if (!sB) {
        cudaStreamCreateWithFlags(&sB, cudaStreamNonBlocking);
        cudaStreamCreateWithFlags(&sC, cudaStreamNonBlocking);
        cudaEventCreateWithFlags(&e0, cudaEventDisableTiming);
        cudaEventCreateWithFlags(&eB, cudaEventDisableTiming);
        cudaEventCreateWithFlags(&eC, cudaEventDisableTiming);
        cudaFuncSetAttribute(gemm_mma_kernel<false>,
                             cudaFuncAttributeMaxDynamicSharedMemorySize, SM_TOTAL);
        cudaFuncSetAttribute(gemm_mma_kernel<true>,
                             cudaFuncAttributeMaxDynamicSharedMemorySize, SM_TOTAL);
    }

    const int GEMM_GRID = (NN + 127) / 128;   // 391
    const int WARP_GRID = NN / 8;             // 6250

    // ---- fork: preprocessing on sB, layer-2/3 weight conversion on sC ----
    cudaEventRecord(e0, 0);
    cudaStreamWaitEvent(sB, e0, 0);
    cudaStreamWaitEvent(sC, e0, 0);

    init_kernel<<<(NN + 255) / 256, 256, 0, sB>>>(ei);
    deg_count_kernel<<<(EE + 255) / 256, 256, 0, sB>>>(ei);
    blocksum_kernel<<<NB, 256, 0, sB>>>();
    scan_bsums_kernel<<<1, 256, 0, sB>>>();
    scatter_scan_kernel<<<NB, 256, 0, sB>>>();
    fill_kernel<<<(EE + 255) / 256, 256, 0, sB>>>(ei);
    cudaEventRecord(eB, sB);

    conv_w_kernel<<<64, 256, 0, sC>>>(W2, wh2, wl2);
    conv_w_kernel<<<64, 256, 0, sC>>>(W3, wh3, wl3);
    cudaEventRecord(eC, sC);

    // ---- main stream: layer 1 GEMM overlaps preprocessing ----
    conv_w_kernel<<<64, 256>>>(W1, wh1, wl1);
    gemm_mma_kernel<false><<<GEMM_GRID, 256, SM_TOTAL>>>(
        x, wh1, wl1, nullptr, nullptr, nullptr, nullptr, d_h);

    cudaStreamWaitEvent(0, eB, 0);   // CSR + stats-zero ready
    agg_stats_kernel<<<WARP_GRID, 256>>>(d_h, d_agg, sum0, sq0);

    // ---- layer 2 (BN params computed in-block from stats buf 0) ----
    cudaStreamWaitEvent(0, eC, 0);   // W2/W3 conversions ready
    gemm_mma_kernel<true><<<GEMM_GRID, 256, SM_TOTAL>>>(
        d_agg, wh2, wl2, g1, be1, sum0, sq0, d_h);
    agg_stats_kernel<<<WARP_GRID, 256>>>(d_h, d_agg, sum1, sq1);

    // ---- layer 3 (BN from stats buf 1; bias + L2norm fused into agg) ----
    gemm_mma_kernel<true><<<GEMM_GRID, 256, SM_TOTAL>>>(
        d_agg, wh3, wl3, g2, be2, sum1, sq1, d_h);
    agg_final_kernel<<<WARP_GRID, 256>>>(d_h, b3, out);
}

// round 17
// speedup vs baseline: 1.4472x; 1.2423x over previous
#include <cuda_runtime.h>
#include <cuda_bf16.h>
#include <cuda_fp16.h>
#include <math.h>
#include <stdint.h>

#define NN 50000
#define EE 800000
#define DD 128
#define BN_EPS 1e-5f
#define NB 196          // ceil(NN/256) scan blocks

// ---------------- device scratch (no allocations allowed) ----------------
__device__ __half g_h[(size_t)NN * DD];   // post-GEMM activations (fp16)
__device__ __half g_agg[(size_t)NN * DD]; // aggregated (fp16)
__device__ __nv_bfloat16 g_wh[3][DD * DD];  // per-layer W^T hi [n][k]
__device__ __nv_bfloat16 g_wl[3][DD * DD];  // per-layer W^T lo [n][k]
__device__ int   g_deg[NN];
__device__ float g_dinv[NN];
__device__ int   g_rowptr[NN + 1];
__device__ int   g_rowcur[NN];
__device__ uint2 g_cw[EE];                // packed {col, w-bits} per edge
__device__ int   g_bsum[256];
__device__ int   g_boff[256];
__device__ float g_sum[2][DD];            // double-buffered BN stats
__device__ float g_sumsq[2][DD];
__device__ int   g_is64;

// ---------------- edge index access (int32 vs int64 tolerant) -----------
__device__ __forceinline__ int edge_src(const int* ei, int e) {
    return g_is64 ? ei[2 * e] : ei[e];
}
__device__ __forceinline__ int edge_dst(const int* ei, int e) {
    return g_is64 ? ei[2 * (EE + e)] : ei[EE + e];
}

// ---------------- graph preprocessing ----------------
__global__ void init_kernel(const int* __restrict__ ei) {
    int i = blockIdx.x * blockDim.x + threadIdx.x;
    if (i < NN) g_deg[i] = 0;
    if (i < DD) {
        g_sum[0][i] = 0.0f; g_sumsq[0][i] = 0.0f;
        g_sum[1][i] = 0.0f; g_sumsq[1][i] = 0.0f;
    }
    if (i == 0) {
        int is64 = 1;
        #pragma unroll
        for (int j = 1; j < 16; j += 2)
            if (ei[j] != 0) is64 = 0;
        g_is64 = is64;
    }
}

__global__ void deg_count_kernel(const int* __restrict__ ei) {
    int e = blockIdx.x * blockDim.x + threadIdx.x;
    if (e < EE) atomicAdd(&g_deg[edge_dst(ei, e)], 1);
}

__global__ __launch_bounds__(256) void blocksum_kernel() {
    int tid = threadIdx.x;
    int i = blockIdx.x * 256 + tid;
    int v = (i < NN) ? g_deg[i] : 0;
    #pragma unroll
    for (int off = 16; off; off >>= 1)
        v += __shfl_xor_sync(0xffffffffu, v, off);
    __shared__ int ws[8];
    if ((tid & 31) == 0) ws[tid >> 5] = v;
    __syncthreads();
    if (tid == 0) {
        int s = 0;
        #pragma unroll
        for (int w = 0; w < 8; w++) s += ws[w];
        g_bsum[blockIdx.x] = s;
    }
}

__global__ __launch_bounds__(256) void scan_bsums_kernel() {
    __shared__ int sm[256];
    int tid = threadIdx.x;
    int v = (tid < NB) ? g_bsum[tid] : 0;
    sm[tid] = v;
    __syncthreads();
    for (int off = 1; off < 256; off <<= 1) {
        int t = (tid >= off) ? sm[tid - off] : 0;
        __syncthreads();
        sm[tid] += t;
        __syncthreads();
    }
    if (tid < NB) g_boff[tid] = sm[tid] - v;       // exclusive
    if (tid == NB - 1) g_rowptr[NN] = sm[tid];     // total
}

__global__ __launch_bounds__(256) void scatter_scan_kernel() {
    __shared__ int sm[256];
    int tid = threadIdx.x;
    int i = blockIdx.x * 256 + tid;
    int d = (i < NN) ? g_deg[i] : 0;
    sm[tid] = d;
    __syncthreads();
    for (int off = 1; off < 256; off <<= 1) {
        int t = (tid >= off) ? sm[tid - off] : 0;
        __syncthreads();
        sm[tid] += t;
        __syncthreads();
    }
    if (i < NN) {
        int pos = g_boff[blockIdx.x] + sm[tid] - d;
        g_rowptr[i] = pos;
        g_rowcur[i] = pos;
        g_dinv[i] = rsqrtf((float)d + 1.0f);       // +1 self loop
    }
}

__global__ void fill_kernel(const int* __restrict__ ei) {
    int e = blockIdx.x * blockDim.x + threadIdx.x;
    if (e < EE) {
        int d = edge_dst(ei, e);
        int s = edge_src(ei, e);
        int pos = atomicAdd(&g_rowcur[d], 1);
        float w = g_dinv[s] * g_dinv[d];
        g_cw[pos] = make_uint2((uint32_t)s, __float_as_uint(w));
    }
}

// W[k][n] -> W^T hi/lo [n][k]
__global__ void conv_w_kernel(const float* __restrict__ W,
                              __nv_bfloat16* __restrict__ wh,
                              __nv_bfloat16* __restrict__ wl)
{
    int i = blockIdx.x * 256 + threadIdx.x;
    if (i >= DD * DD) return;
    int n = i >> 7, k = i & 127;
    float v = W[k * DD + n];
    __nv_bfloat16 h = __float2bfloat16(v);
    __nv_bfloat16 l = __float2bfloat16(v - __bfloat162float(h));
    wh[i] = h;
    wl[i] = l;
}

// ---------------- HMMA GEMM: h[M,128] = act(A)[M,128] @ W[128,128] -----
// (identical to the 217us baseline)
#define PITCH 72
#define KC 64
#define TILEB (128 * PITCH * 2)   // 18432
#define SM_AHI 0
#define SM_ALO TILEB
#define SM_WHI (2 * TILEB)
#define SM_WLO (3 * TILEB)
#define SM_TOTAL (4 * TILEB)      // 73728

static __device__ __forceinline__ uint32_t smem_u32(const void* p) {
    uint32_t a;
    asm("{ .reg .u64 t; cvta.to.shared.u64 t, %1; cvt.u32.u64 %0, t; }"
        : "=r"(a) : "l"(p));
    return a;
}

__device__ __forceinline__ void ldm_x4(uint32_t* r, uint32_t addr) {
    asm volatile("ldmatrix.sync.aligned.m8n8.x4.shared.b16 {%0,%1,%2,%3}, [%4];"
                 : "=r"(r[0]), "=r"(r[1]), "=r"(r[2]), "=r"(r[3]) : "r"(addr));
}

__device__ __forceinline__ void mma16816(float* d, const uint32_t* a,
                                         uint32_t b0, uint32_t b1) {
    asm volatile(
        "mma.sync.aligned.m16n8k16.row.col.f32.bf16.bf16.f32 "
        "{%0,%1,%2,%3}, {%4,%5,%6,%7}, {%8,%9}, {%0,%1,%2,%3};"
        : "+f"(d[0]), "+f"(d[1]), "+f"(d[2]), "+f"(d[3])
        : "r"(a[0]), "r"(a[1]), "r"(a[2]), "r"(a[3]), "r"(b0), "r"(b1));
}

template<bool BN>
__global__ __launch_bounds__(256, 2)
void gemm_mma_kernel(const void* __restrict__ Avoid,
                     const __nv_bfloat16* __restrict__ Wh,
                     const __nv_bfloat16* __restrict__ Wl,
                     const float* __restrict__ gamma,
                     const float* __restrict__ beta,
                     const float* __restrict__ gsum,
                     const float* __restrict__ gsq,
                     __half* __restrict__ C)
{
    extern __shared__ char smem[];
    __shared__ float s_scale[DD];
    __shared__ float s_shift[DD];
    uint32_t sbase = smem_u32(smem);
    int tid = threadIdx.x;
    int wid = tid >> 5;
    int lane = tid & 31;
    int m0blk = blockIdx.x * 128;
    int wm = (wid & 3) * 32;
    int wn = (wid >> 2) * 64;

    if (BN && tid < DD) {
        float mu = gsum[tid] * (1.0f / NN);
        float var = gsq[tid] * (1.0f / NN) - mu * mu;
        float sc = gamma[tid] * rsqrtf(var + BN_EPS);
        s_scale[tid] = sc;
        s_shift[tid] = beta[tid] - mu * sc;
    }
    if (BN) __syncthreads();

    float acc[2][8][4];
    #pragma unroll
    for (int mt = 0; mt < 2; mt++)
        #pragma unroll
        for (int nt = 0; nt < 8; nt++)
            #pragma unroll
            for (int q = 0; q < 4; q++) acc[mt][nt][q] = 0.0f;

    int a_row = (lane & 7) + 8 * ((lane >> 3) & 1);
    int a_kof = 8 * (lane >> 4);
    int b_nof = (lane & 7) + 8 * (lane >> 4);
    int b_kof = 8 * ((lane >> 3) & 1);

    #pragma unroll
    for (int kc = 0; kc < 2; kc++) {
        int kbase = kc * KC;
        if (kc) __syncthreads();

        for (int idx = tid; idx < 2048; idx += 256) {
            int r = idx >> 4;
            int c4 = (idx & 15) * 4;
            int gc = kbase + c4;
            float4 v = make_float4(0.f, 0.f, 0.f, 0.f);
            if (m0blk + r < NN) {
                if (BN) {
                    const __half* Ah16 = (const __half*)Avoid;
                    uint2 raw = *(const uint2*)(Ah16 + (size_t)(m0blk + r) * DD + gc);
                    float2 f0 = __half22float2(*(__half2*)&raw.x);
                    float2 f1 = __half22float2(*(__half2*)&raw.y);
                    v = make_float4(f0.x, f0.y, f1.x, f1.y);
                } else {
                    const float* Af = (const float*)Avoid;
                    v = *(const float4*)(Af + (size_t)(m0blk + r) * DD + gc);
                }
            }
            if (BN) {
                v.x = fmaxf(fmaf(v.x, s_scale[gc + 0], s_shift[gc + 0]), 0.0f);
                v.y = fmaxf(fmaf(v.y, s_scale[gc + 1], s_shift[gc + 1]), 0.0f);
                v.z = fmaxf(fmaf(v.z, s_scale[gc + 2], s_shift[gc + 2]), 0.0f);
                v.w = fmaxf(fmaf(v.w, s_scale[gc + 3], s_shift[gc + 3]), 0.0f);
            }
            float a[4] = {v.x, v.y, v.z, v.w};
            uint32_t ph[2], pl[2];
            #pragma unroll
            for (int p = 0; p < 2; p++) {
                __nv_bfloat16 h0 = __float2bfloat16(a[2 * p]);
                __nv_bfloat16 h1 = __float2bfloat16(a[2 * p + 1]);
                __nv_bfloat16 l0 = __float2bfloat16(a[2 * p] - __bfloat162float(h0));
                __nv_bfloat16 l1 = __float2bfloat16(a[2 * p + 1] - __bfloat162float(h1));
                ph[p] = (uint32_t)__bfloat16_as_ushort(h0) | ((uint32_t)__bfloat16_as_ushort(h1) << 16);
                pl[p] = (uint32_t)__bfloat16_as_ushort(l0) | ((uint32_t)__bfloat16_as_ushort(l1) << 16);
            }
            size_t boff = ((size_t)r * PITCH + c4) * 2;
            *(uint2*)(smem + SM_AHI + boff) = make_uint2(ph[0], ph[1]);
            *(uint2*)(smem + SM_ALO + boff) = make_uint2(pl[0], pl[1]);
        }
        for (int idx = tid; idx < 1024; idx += 256) {
            int n = idx >> 3;
            int kq = (idx & 7) * 8;
            uint4 vh = *(const uint4*)(Wh + (size_t)n * DD + kbase + kq);
            uint4 vl = *(const uint4*)(Wl + (size_t)n * DD + kbase + kq);
            size_t boff = ((size_t)n * PITCH + kq) * 2;
            *(uint4*)(smem + SM_WHI + boff) = vh;
            *(uint4*)(smem + SM_WLO + boff) = vl;
        }
        __syncthreads();

        #pragma unroll
        for (int k0 = 0; k0 < KC; k0 += 16) {
            uint32_t aH[2][4], aL[2][4];
            #pragma unroll
            for (int mt = 0; mt < 2; mt++) {
                uint32_t ad = sbase + SM_AHI
                    + ((uint32_t)(wm + mt * 16 + a_row) * PITCH + k0 + a_kof) * 2;
                ldm_x4(aH[mt], ad);
                ldm_x4(aL[mt], ad + (SM_ALO - SM_AHI));
            }
            #pragma unroll
            for (int ng = 0; ng < 4; ng++) {
                uint32_t bH[4], bL[4];
                uint32_t bd = sbase + SM_WHI
                    + ((uint32_t)(wn + ng * 16 + b_nof) * PITCH + k0 + b_kof) * 2;
                ldm_x4(bH, bd);
                ldm_x4(bL, bd + (SM_WLO - SM_WHI));
                #pragma unroll
                for (int mt = 0; mt < 2; mt++)
                    #pragma unroll
                    for (int half = 0; half < 2; half++) {
                        int nt = ng * 2 + half;
                        int s = half * 2;
                        mma16816(acc[mt][nt], aH[mt], bH[s], bH[s + 1]);
                        mma16816(acc[mt][nt], aH[mt], bL[s], bL[s + 1]);
                        mma16816(acc[mt][nt], aL[mt], bH[s], bH[s + 1]);
                    }
            }
        }
    }

    #pragma unroll
    for (int mt = 0; mt < 2; mt++) {
        int row0 = m0blk + wm + mt * 16 + (lane >> 2);
        int row1 = row0 + 8;
        #pragma unroll
        for (int nt = 0; nt < 8; nt++) {
            int col = wn + nt * 8 + (lane & 3) * 2;
            if (row0 < NN)
                *(__half2*)(C + (size_t)row0 * DD + col) =
                    __floats2half2_rn(acc[mt][nt][0], acc[mt][nt][1]);
            if (row1 < NN)
                *(__half2*)(C + (size_t)row1 * DD + col) =
                    __floats2half2_rn(acc[mt][nt][2], acc[mt][nt][3]);
        }
    }
}

// ---------------- fp16 gather helper ----------------
__device__ __forceinline__ void acc_edge(float4& acc, const __half* __restrict__ h,
                                         int s, int lane, float w)
{
    uint2 raw = *(const uint2*)(h + (size_t)s * DD + lane * 4);
    float2 f0 = __half22float2(*(__half2*)&raw.x);
    float2 f1 = __half22float2(*(__half2*)&raw.y);
    acc.x = fmaf(f0.x, w, acc.x);
    acc.y = fmaf(f0.y, w, acc.y);
    acc.z = fmaf(f1.x, w, acc.z);
    acc.w = fmaf(f1.y, w, acc.w);
}

// ---------------- aggregation + fused BN statistics (fp16 out) ----------
__global__ __launch_bounds__(256) void agg_stats_kernel(
    const __half* __restrict__ h, __half* __restrict__ out,
    float* __restrict__ gsum, float* __restrict__ gsq)
{
    __shared__ float ssum[DD];
    __shared__ float ssq[DD];
    int tid = threadIdx.x;
    if (tid < DD) { ssum[tid] = 0.0f; ssq[tid] = 0.0f; }
    __syncthreads();

    int gw = (blockIdx.x * blockDim.x + tid) >> 5;
    int lane = tid & 31;

    if (gw < NN) {
        float di = g_dinv[gw];
        float4 acc = make_float4(0.f, 0.f, 0.f, 0.f);
        acc_edge(acc, h, gw, lane, di * di);   // self loop

        int beg = g_rowptr[gw];
        int end = g_rowptr[gw + 1];
        int e = beg;
        for (; e + 3 < end; e += 4) {
            uint2 c0 = g_cw[e],     c1 = g_cw[e + 1];
            uint2 c2 = g_cw[e + 2], c3 = g_cw[e + 3];
            acc_edge(acc, h, (int)c0.x, lane, __uint_as_float(c0.y));
            acc_edge(acc, h, (int)c1.x, lane, __uint_as_float(c1.y));
            acc_edge(acc, h, (int)c2.x, lane, __uint_as_float(c2.y));
            acc_edge(acc, h, (int)c3.x, lane, __uint_as_float(c3.y));
        }
        for (; e < end; e++) {
            uint2 c = g_cw[e];
            acc_edge(acc, h, (int)c.x, lane, __uint_as_float(c.y));
        }

        uint2 packed;
        *(__half2*)&packed.x = __floats2half2_rn(acc.x, acc.y);
        *(__half2*)&packed.y = __floats2half2_rn(acc.z, acc.w);
        *(uint2*)(out + (size_t)gw * DD + lane * 4) = packed;

        int f = lane * 4;
        atomicAdd(&ssum[f + 0], acc.x);
        atomicAdd(&ssum[f + 1], acc.y);
        atomicAdd(&ssum[f + 2], acc.z);
        atomicAdd(&ssum[f + 3], acc.w);
        atomicAdd(&ssq[f + 0], acc.x * acc.x);
        atomicAdd(&ssq[f + 1], acc.y * acc.y);
        atomicAdd(&ssq[f + 2], acc.z * acc.z);
        atomicAdd(&ssq[f + 3], acc.w * acc.w);
    }
    __syncthreads();
    if (tid < DD) {
        atomicAdd(&gsum[tid], ssum[tid]);
        atomicAdd(&gsq[tid], ssq[tid]);
    }
}

// ---------------- final aggregation + bias + L2 normalize ----------------
__global__ __launch_bounds__(256) void agg_final_kernel(
    const __half* __restrict__ h, const float* __restrict__ b3,
    float* __restrict__ out)
{
    int gw = (blockIdx.x * blockDim.x + threadIdx.x) >> 5;
    int lane = threadIdx.x & 31;
    if (gw >= NN) return;

    float di = g_dinv[gw];
    float4 acc = make_float4(0.f, 0.f, 0.f, 0.f);
    acc_edge(acc, h, gw, lane, di * di);   // self loop

    int beg = g_rowptr[gw];
    int end = g_rowptr[gw + 1];
    int e = beg;
    for (; e + 3 < end; e += 4) {
        uint2 c0 = g_cw[e],     c1 = g_cw[e + 1];
        uint2 c2 = g_cw[e + 2], c3 = g_cw[e + 3];
        acc_edge(acc, h, (int)c0.x, lane, __uint_as_float(c0.y));
        acc_edge(acc, h, (int)c1.x, lane, __uint_as_float(c1.y));
        acc_edge(acc, h, (int)c2.x, lane, __uint_as_float(c2.y));
        acc_edge(acc, h, (int)c3.x, lane, __uint_as_float(c3.y));
    }
    for (; e < end; e++) {
        uint2 c = g_cw[e];
        acc_edge(acc, h, (int)c.x, lane, __uint_as_float(c.y));
    }

    float4 bb = ((const float4*)b3)[lane];
    acc.x += bb.x; acc.y += bb.y; acc.z += bb.z; acc.w += bb.w;
    float ss = acc.x * acc.x + acc.y * acc.y + acc.z * acc.z + acc.w * acc.w;
    #pragma unroll
    for (int off = 16; off; off >>= 1)
        ss += __shfl_xor_sync(0xffffffffu, ss, off);
    float inv = 1.0f / fmaxf(sqrtf(ss), 1e-12f);
    float4 o = make_float4(acc.x * inv, acc.y * inv, acc.z * inv, acc.w * inv);
    *(float4*)(out + (size_t)gw * DD + lane * 4) = o;
}

// ---------------- launch ----------------
extern "C" void kernel_launch(void* const* d_in, const int* in_sizes, int n_in,
                              void* d_out, int out_size)
{
    const float* x   = (const float*)d_in[0];
    const int*   ei  = (const int*)d_in[1];
    const float* W1  = (const float*)d_in[2];
    // b1 = d_in[3]  -- no-op before BatchNorm
    const float* W2  = (const float*)d_in[4];
    // b2 = d_in[5]  -- no-op before BatchNorm
    const float* W3  = (const float*)d_in[6];
    const float* b3  = (const float*)d_in[7];
    const float* g1  = (const float*)d_in[8];
    const float* be1 = (const float*)d_in[9];
    const float* g2  = (const float*)d_in[10];
    const float* be2 = (const float*)d_in[11];
    float* out = (float*)d_out;

    __half* d_h;   cudaGetSymbolAddress((void**)&d_h,   g_h);
    __half* d_agg; cudaGetSymbolAddress((void**)&d_agg, g_agg);
    __nv_bfloat16* d_wh; cudaGetSymbolAddress((void**)&d_wh, g_wh);
    __nv_bfloat16* d_wl; cudaGetSymbolAddress((void**)&d_wl, g_wl);
    float* d_sum; cudaGetSymbolAddress((void**)&d_sum, g_sum);
    float* d_sq;  cudaGetSymbolAddress((void**)&d_sq,  g_sumsq);
    __nv_bfloat16* wh1 = d_wh,               *wl1 = d_wl;
    __nv_bfloat16* wh2 = d_wh + DD * DD,     *wl2 = d_wl + DD * DD;
    __nv_bfloat16* wh3 = d_wh + 2 * DD * DD, *wl3 = d_wl + 2 * DD * DD;
    float* sum0 = d_sum, *sq0 = d_sq;
    float* sum1 = d_sum + DD, *sq1 = d_sq + DD;

    static cudaStream_t sB = nullptr, sC = nullptr;
    static cudaEvent_t e0 = nullptr, eB = nullptr, eC = nullptr;
    if (!sB) {
        cudaStreamCreateWithFlags(&sB, cudaStreamNonBlocking);
        cudaStreamCreateWithFlags(&sC, cudaStreamNonBlocking);
        cudaEventCreateWithFlags(&e0, cudaEventDisableTiming);
        cudaEventCreateWithFlags(&eB, cudaEventDisableTiming);
        cudaEventCreateWithFlags(&eC, cudaEventDisableTiming);
        cudaFuncSetAttribute(gemm_mma_kernel<false>,
                             cudaFuncAttributeMaxDynamicSharedMemorySize, SM_TOTAL);
        cudaFuncSetAttribute(gemm_mma_kernel<true>,
                             cudaFuncAttributeMaxDynamicSharedMemorySize, SM_TOTAL);
    }

    const int GEMM_GRID = (NN + 127) / 128;   // 391
    const int WARP_GRID = NN / 8;             // 6250

    // ---- fork: preprocessing on sB, layer-2/3 weight conversion on sC ----
    cudaEventRecord(e0, 0);
    cudaStreamWaitEvent(sB, e0, 0);
    cudaStreamWaitEvent(sC, e0, 0);

    init_kernel<<<(NN + 255) / 256, 256, 0, sB>>>(ei);
    deg_count_kernel<<<(EE + 255) / 256, 256, 0, sB>>>(ei);
    blocksum_kernel<<<NB, 256, 0, sB>>>();
    scan_bsums_kernel<<<1, 256, 0, sB>>>();
    scatter_scan_kernel<<<NB, 256, 0, sB>>>();
    fill_kernel<<<(EE + 255) / 256, 256, 0, sB>>>(ei);
    cudaEventRecord(eB, sB);

    conv_w_kernel<<<64, 256, 0, sC>>>(W2, wh2, wl2);
    conv_w_kernel<<<64, 256, 0, sC>>>(W3, wh3, wl3);
    cudaEventRecord(eC, sC);

    // ---- main stream: layer 1 GEMM overlaps preprocessing ----
    conv_w_kernel<<<64, 256>>>(W1, wh1, wl1);
    gemm_mma_kernel<false><<<GEMM_GRID, 256, SM_TOTAL>>>(
        x, wh1, wl1, nullptr, nullptr, nullptr, nullptr, d_h);

    cudaStreamWaitEvent(0, eB, 0);   // CSR + stats-zero ready
    agg_stats_kernel<<<WARP_GRID, 256>>>(d_h, d_agg, sum0, sq0);

    // ---- layer 2 (BN params computed in-block from stats buf 0) ----
    cudaStreamWaitEvent(0, eC, 0);   // W2/W3 conversions ready
    gemm_mma_kernel<true><<<GEMM_GRID, 256, SM_TOTAL>>>(
        d_agg, wh2, wl2, g1, be1, sum0, sq0, d_h);
    agg_stats_kernel<<<WARP_GRID, 256>>>(d_h, d_agg, sum1, sq1);

    // ---- layer 3 (BN from stats buf 1; bias + L2norm fused into agg) ----
    gemm_mma_kernel<true><<<GEMM_GRID, 256, SM_TOTAL>>>(
        d_agg, wh3, wl3, g2, be2, sum1, sq1, d_h);
    agg_final_kernel<<<WARP_GRID, 256>>>(d_h, b3, out);
}